// round 5
// baseline (speedup 1.0000x reference)
#include <cuda_runtime.h>
#include <cuda_bf16.h>
#include <math.h>
#include <stdint.h>

// ---------------------------------------------------------------------------
// Swin Transformer block: B=32, H=W=56, C=384, 12 heads, window 7, shift 3
// ---------------------------------------------------------------------------
#define Bb    32
#define Hh    56
#define Ww    56
#define Cc    384
#define HEADS 12
#define WS    7
#define SHIFT 3
#define HD    32
#define NTOK  49
#define NWIN  64
#define ROWS  100352
#define C3    1152
#define CH    1536
#define SCALE 0.17677669529663687f
#define LNEPS 1e-5f

// Scratch (static device memory — no allocation at runtime)
__device__ float g_win[(size_t)ROWS * Cc];
__device__ float g_qkv[(size_t)ROWS * C3];
__device__ float g_xa [(size_t)ROWS * Cc];
__device__ float g_m1 [(size_t)ROWS * CH];
// tf32-rounded weights: qkv | proj | fc1 | fc2
#define W_QKV 0
#define W_PROJ (Cc * C3)
#define W_FC1  (W_PROJ + Cc * Cc)
#define W_FC2  (W_FC1 + Cc * CH)
#define W_TOT  (W_FC2 + CH * Cc)
__device__ float g_wc[W_TOT];

__device__ __forceinline__ uint32_t f2tf32(float x)
{
    uint32_t u;
    asm("cvt.rna.tf32.f32 %0, %1;" : "=r"(u) : "f"(x));
    return u;
}
__device__ __forceinline__ float roundtf(float x)
{
    return __uint_as_float(f2tf32(x));
}

// ---------------------------------------------------------------------------
// Weight convert (fp32 -> tf32-rounded fp32), one-time per launch
// ---------------------------------------------------------------------------
__global__ void __launch_bounds__(256) cvt_kernel(
    const float* __restrict__ src, float* __restrict__ dst, int n)
{
    int i = blockIdx.x * 256 + threadIdx.x;
    if (i < n) dst[i] = roundtf(src[i]);
}

// ---------------------------------------------------------------------------
// LayerNorm (fused shift+window-partition gather when gather==1).
// Output is tf32-rounded (it is only ever consumed as GEMM A).
// ---------------------------------------------------------------------------
__global__ void __launch_bounds__(128) ln_kernel(
    const float* __restrict__ x, const float* __restrict__ g,
    const float* __restrict__ bt, float* __restrict__ out, int gather)
{
    int r = blockIdx.x;
    int src = r;
    if (gather) {
        int n  = r % NTOK;
        int wl = (r / NTOK) % NWIN;
        int b  = r / (NTOK * NWIN);
        int wh = wl >> 3, ww = wl & 7;
        int i  = n / WS,  j  = n % WS;
        int oh = (wh * WS + i + SHIFT) % Hh;
        int ow = (ww * WS + j + SHIFT) % Ww;
        src = b * (Hh * Ww) + oh * Ww + ow;
    }
    const float* xp = x + (size_t)src * Cc;
    int tid = threadIdx.x;
    float v[3];
#pragma unroll
    for (int q = 0; q < 3; q++) v[q] = xp[tid + q * 128];
    float s  = v[0] + v[1] + v[2];
    float s2 = v[0]*v[0] + v[1]*v[1] + v[2]*v[2];
#pragma unroll
    for (int o = 16; o; o >>= 1) {
        s  += __shfl_xor_sync(0xffffffffu, s,  o);
        s2 += __shfl_xor_sync(0xffffffffu, s2, o);
    }
    __shared__ float sh[8];
    int wid = tid >> 5, lane = tid & 31;
    if (lane == 0) { sh[wid] = s; sh[wid + 4] = s2; }
    __syncthreads();
    float mu  = (sh[0] + sh[1] + sh[2] + sh[3]) * (1.0f / Cc);
    float var = (sh[4] + sh[5] + sh[6] + sh[7]) * (1.0f / Cc) - mu * mu;
    float rstd = rsqrtf(var + LNEPS);
    float* op = out + (size_t)r * Cc;
#pragma unroll
    for (int q = 0; q < 3; q++) {
        int c = tid + q * 128;
        op[c] = roundtf((v[q] - mu) * rstd * g[c] + bt[c]);
    }
}

__device__ __forceinline__ int winrev_map(int m)
{
    int n  = m % NTOK;
    int wl = (m / NTOK) % NWIN;
    int b  = m / (NTOK * NWIN);
    int wh = wl >> 3, ww = wl & 7;
    int i  = n / WS,  j  = n % WS;
    int oh = (wh * WS + i + SHIFT) % Hh;
    int ow = (ww * WS + j + SHIFT) % Ww;
    return b * (Hh * Ww) + oh * Ww + ow;
}

__device__ __forceinline__ void cpa16(uint32_t dst, const void* src)
{
    asm volatile("cp.async.ca.shared.global [%0], [%1], 16;" :: "r"(dst), "l"(src));
}

// ---------------------------------------------------------------------------
// TF32 tensor-core GEMM: C = A[M,K] @ B[K,N] + bias (+ fused epilogues)
// Inputs are pre-rounded to tf32. Block 128x128x16, 4 warps (64x64 each),
// 3-stage cp.async pipeline. mma.sync.m16n8k8.tf32.
// SMEM pads: A[128][20] and B[16][136] give conflict-free fragment loads.
// EPI 0: store. 1: window-reverse scatter + shortcut add. 2: GELU (+round).
// 3: residual add.
// ---------------------------------------------------------------------------
#define ST 3
#define SA_ELEM (128 * 20)
#define SB_ELEM (16 * 136)

template <int EPI>
__global__ void __launch_bounds__(128) mma_gemm(
    const float* __restrict__ A, const float* __restrict__ Bw,
    const float* __restrict__ bias, float* __restrict__ Cout,
    int M, int N, int K, const float* __restrict__ add_src)
{
    extern __shared__ float smem[];
    float* sA = smem;                   // [ST][128*20]
    float* sB = smem + ST * SA_ELEM;    // [ST][16*136]

    const int tid  = threadIdx.x;
    const int lane = tid & 31;
    const int wid  = tid >> 5;          // 4 warps
    const int wm   = (wid & 1) * 64;
    const int wn   = (wid >> 1) * 64;
    const int m0   = blockIdx.y * 128;
    const int n0   = blockIdx.x * 128;

    // cp.async source mapping: A -> one row per thread (4x16B chunks);
    // B -> row tid>>3, 4 chunks of 16B spread across the 128-col tile.
    const float* gA = A + (size_t)(m0 + tid) * K;
    const int    bR = tid >> 3;          // 0..15
    const int    bC = (tid & 7) * 4;     // element col base within group
    const float* gB = Bw + (size_t)bR * N + n0 + bC;

    uint32_t aDst = (uint32_t)__cvta_generic_to_shared(&sA[tid * 20]);
    uint32_t bDst = (uint32_t)__cvta_generic_to_shared(&sB[bR * 136 + bC]);

    const int KT = K >> 4;

    auto issue = [&](int s, int k0) {
        uint32_t ad = aDst + s * SA_ELEM * 4;
        const float* as = gA + k0;
#pragma unroll
        for (int c = 0; c < 4; c++) cpa16(ad + c * 16, as + c * 4);
        uint32_t bd = bDst + s * SB_ELEM * 4;
        const float* bs = gB + (size_t)k0 * N;
#pragma unroll
        for (int q = 0; q < 4; q++) cpa16(bd + q * 128, bs + q * 32);
        asm volatile("cp.async.commit_group;");
    };

    issue(0, 0);
    if (KT > 1) issue(1, 16); else asm volatile("cp.async.commit_group;");

    float c[4][8][4] = {};

    // fragment base pointers
    const float* pA0 = sA + (wm + (lane >> 2)) * 20 + (lane & 3);
    const float* pB0 = sB + (lane & 3) * 136 + wn + (lane >> 2);

    for (int kt = 0; kt < KT; kt++) {
        if (kt + 1 < KT) asm volatile("cp.async.wait_group 1;");
        else             asm volatile("cp.async.wait_group 0;");
        __syncthreads();

        int s = kt % ST;
        const float* pA = pA0 + s * SA_ELEM;
        const float* pB = pB0 + s * SB_ELEM;
#pragma unroll
        for (int kk = 0; kk < 16; kk += 8) {
            uint32_t af[4][4], bf[8][2];
#pragma unroll
            for (int i = 0; i < 4; i++) {
                af[i][0] = __float_as_uint(pA[(i * 16) * 20 + kk]);
                af[i][1] = __float_as_uint(pA[(i * 16 + 8) * 20 + kk]);
                af[i][2] = __float_as_uint(pA[(i * 16) * 20 + kk + 4]);
                af[i][3] = __float_as_uint(pA[(i * 16 + 8) * 20 + kk + 4]);
            }
#pragma unroll
            for (int j = 0; j < 8; j++) {
                bf[j][0] = __float_as_uint(pB[kk * 136 + j * 8]);
                bf[j][1] = __float_as_uint(pB[(kk + 4) * 136 + j * 8]);
            }
#pragma unroll
            for (int i = 0; i < 4; i++)
#pragma unroll
                for (int j = 0; j < 8; j++)
                    asm volatile(
                        "mma.sync.aligned.m16n8k8.row.col.f32.tf32.tf32.f32 "
                        "{%0,%1,%2,%3}, {%4,%5,%6,%7}, {%8,%9}, {%0,%1,%2,%3};"
                        : "+f"(c[i][j][0]), "+f"(c[i][j][1]),
                          "+f"(c[i][j][2]), "+f"(c[i][j][3])
                        : "r"(af[i][0]), "r"(af[i][1]), "r"(af[i][2]), "r"(af[i][3]),
                          "r"(bf[j][0]), "r"(bf[j][1]));
        }
        __syncthreads();
        if (kt + 2 < KT) issue((kt + 2) % ST, (kt + 2) * 16);
    }

    // epilogue
#pragma unroll
    for (int i = 0; i < 4; i++) {
#pragma unroll
        for (int half = 0; half < 2; half++) {
            int r = m0 + wm + i * 16 + (lane >> 2) + half * 8;
            int dest = (EPI == 1) ? winrev_map(r) : r;
#pragma unroll
            for (int j = 0; j < 8; j++) {
                int cn = n0 + wn + j * 8 + (lane & 3) * 2;
                float v0 = c[i][j][half * 2 + 0] + bias[cn];
                float v1 = c[i][j][half * 2 + 1] + bias[cn + 1];
                if (EPI == 0) {
                    *(float2*)&Cout[(size_t)r * N + cn] = make_float2(v0, v1);
                } else if (EPI == 1) {
                    size_t idx = (size_t)dest * Cc + cn;
                    *(float2*)&Cout[idx] =
                        make_float2(add_src[idx] + v0, add_src[idx + 1] + v1);
                } else if (EPI == 2) {
                    v0 = 0.5f * v0 * (1.0f + erff(v0 * 0.70710678118654752f));
                    v1 = 0.5f * v1 * (1.0f + erff(v1 * 0.70710678118654752f));
                    *(float2*)&Cout[(size_t)r * N + cn] =
                        make_float2(roundtf(v0), roundtf(v1));
                } else { // EPI == 3
                    size_t idx = (size_t)r * N + cn;
                    *(float2*)&Cout[idx] =
                        make_float2(add_src[idx] + v0, add_src[idx + 1] + v1);
                }
            }
        }
    }
}

// ---------------------------------------------------------------------------
// Windowed attention: one block per (window, head). N=49, HD=32.
// Output rounded to tf32 (consumed as GEMM A by proj).
// ---------------------------------------------------------------------------
__global__ void __launch_bounds__(64) attn_kernel(
    const float* __restrict__ qkv, const float* __restrict__ rpb,
    float* __restrict__ xa)
{
    int head = blockIdx.x;
    int bwin = blockIdx.y;
    __shared__ float qs[NTOK * HD], ks[NTOK * HD], vs[NTOK * HD];
    int tid = threadIdx.x;

    const float* base = qkv + (size_t)bwin * NTOK * C3 + head * HD;
    for (int idx = tid; idx < NTOK * HD; idx += 64) {
        int n = idx >> 5, d = idx & 31;
        size_t off = (size_t)n * C3 + d;
        qs[idx] = base[off];
        ks[idx] = base[off + Cc];
        vs[idx] = base[off + 2 * Cc];
    }
    __syncthreads();

    if (tid < NTOK) {
        int n = tid;
        float q[HD];
#pragma unroll
        for (int d = 0; d < HD; d++) q[d] = qs[n * HD + d] * SCALE;

        int in_ = n / WS, jn = n % WS;
        int wl = bwin & (NWIN - 1);
        int wh = wl >> 3, ww = wl & 7;
        int hs_n = wh * WS + in_, ws_n = ww * WS + jn;
        int lab_n = (hs_n < Hh - WS ? 0 : (hs_n < Hh - SHIFT ? 1 : 2)) * 3
                  + (ws_n < Ww - WS ? 0 : (ws_n < Ww - SHIFT ? 1 : 2));

        float s[NTOK];
        float mx = -1e30f;
        for (int m = 0; m < NTOK; m++) {
            float dot = 0.0f;
#pragma unroll
            for (int d = 0; d < HD; d++) dot += q[d] * ks[m * HD + d];
            int im = m / WS, jm = m % WS;
            int hs_m = wh * WS + im, ws_m = ww * WS + jm;
            int lab_m = (hs_m < Hh - WS ? 0 : (hs_m < Hh - SHIFT ? 1 : 2)) * 3
                      + (ws_m < Ww - WS ? 0 : (ws_m < Ww - SHIFT ? 1 : 2));
            int rel = (in_ - im + WS - 1) * (2 * WS - 1) + (jn - jm + WS - 1);
            dot += rpb[rel * HEADS + head];
            if (lab_m != lab_n) dot -= 100.0f;
            s[m] = dot;
            mx = fmaxf(mx, dot);
        }
        float sum = 0.0f;
        for (int m = 0; m < NTOK; m++) { s[m] = __expf(s[m] - mx); sum += s[m]; }
        float inv = 1.0f / sum;

        float o[HD];
#pragma unroll
        for (int d = 0; d < HD; d++) o[d] = 0.0f;
        for (int m = 0; m < NTOK; m++) {
            float p = s[m] * inv;
#pragma unroll
            for (int d = 0; d < HD; d++) o[d] += p * vs[m * HD + d];
        }
        float* dst = xa + ((size_t)bwin * NTOK + n) * Cc + head * HD;
#pragma unroll
        for (int d = 0; d < HD; d++) dst[d] = roundtf(o[d]);
    }
}

// ---------------------------------------------------------------------------
// Launch
// ---------------------------------------------------------------------------
extern "C" void kernel_launch(void* const* d_in, const int* in_sizes, int n_in,
                              void* d_out, int out_size)
{
    const float* x      = (const float*)d_in[0];
    const float* ln1_g  = (const float*)d_in[1];
    const float* ln1_b  = (const float*)d_in[2];
    const float* qkv_w  = (const float*)d_in[3];
    const float* qkv_b  = (const float*)d_in[4];
    const float* rpb    = (const float*)d_in[5];
    const float* proj_w = (const float*)d_in[6];
    const float* proj_b = (const float*)d_in[7];
    const float* ln2_g  = (const float*)d_in[8];
    const float* ln2_b  = (const float*)d_in[9];
    const float* fc1_w  = (const float*)d_in[10];
    const float* fc1_b  = (const float*)d_in[11];
    const float* fc2_w  = (const float*)d_in[12];
    const float* fc2_b  = (const float*)d_in[13];
    float* out = (float*)d_out;

    float *p_win, *p_qkv, *p_xa, *p_m1, *p_wc;
    cudaGetSymbolAddress((void**)&p_win, g_win);
    cudaGetSymbolAddress((void**)&p_qkv, g_qkv);
    cudaGetSymbolAddress((void**)&p_xa,  g_xa);
    cudaGetSymbolAddress((void**)&p_m1,  g_m1);
    cudaGetSymbolAddress((void**)&p_wc,  g_wc);

    const int smem_bytes = (ST * SA_ELEM + ST * SB_ELEM) * 4;
    cudaFuncSetAttribute(mma_gemm<0>, cudaFuncAttributeMaxDynamicSharedMemorySize, smem_bytes);
    cudaFuncSetAttribute(mma_gemm<1>, cudaFuncAttributeMaxDynamicSharedMemorySize, smem_bytes);
    cudaFuncSetAttribute(mma_gemm<2>, cudaFuncAttributeMaxDynamicSharedMemorySize, smem_bytes);
    cudaFuncSetAttribute(mma_gemm<3>, cudaFuncAttributeMaxDynamicSharedMemorySize, smem_bytes);

    // 0. one-time weight converts (tf32 rounding)
    cvt_kernel<<<(Cc * C3 + 255) / 256, 256>>>(qkv_w,  p_wc + W_QKV, Cc * C3);
    cvt_kernel<<<(Cc * Cc + 255) / 256, 256>>>(proj_w, p_wc + W_PROJ, Cc * Cc);
    cvt_kernel<<<(Cc * CH + 255) / 256, 256>>>(fc1_w,  p_wc + W_FC1, Cc * CH);
    cvt_kernel<<<(CH * Cc + 255) / 256, 256>>>(fc2_w,  p_wc + W_FC2, CH * Cc);

    // 1. LN1 + shift + window partition (tf32-rounded out)
    ln_kernel<<<ROWS, 128>>>(x, ln1_g, ln1_b, p_win, 1);

    // 2. qkv GEMM: [ROWS,384] @ [384,1152]
    mma_gemm<0><<<dim3(C3 / 128, ROWS / 128), 128, smem_bytes>>>(
        p_win, p_wc + W_QKV, qkv_b, p_qkv, ROWS, C3, Cc, nullptr);

    // 3. windowed attention
    attn_kernel<<<dim3(HEADS, ROWS / NTOK), 64>>>(p_qkv, rpb, p_xa);

    // 4. proj GEMM + window reverse + unshift + shortcut add -> d_out
    mma_gemm<1><<<dim3(Cc / 128, ROWS / 128), 128, smem_bytes>>>(
        p_xa, p_wc + W_PROJ, proj_b, out, ROWS, Cc, Cc, x);

    // 5. LN2 on d_out (tf32-rounded out)
    ln_kernel<<<ROWS, 128>>>(out, ln2_g, ln2_b, p_win, 0);

    // 6. fc1 GEMM + GELU: [ROWS,384] @ [384,1536]
    mma_gemm<2><<<dim3(CH / 128, ROWS / 128), 128, smem_bytes>>>(
        p_win, p_wc + W_FC1, fc1_b, p_m1, ROWS, CH, Cc, nullptr);

    // 7. fc2 GEMM + residual add: [ROWS,1536] @ [1536,384]
    mma_gemm<3><<<dim3(Cc / 128, ROWS / 128), 128, smem_bytes>>>(
        p_m1, p_wc + W_FC2, fc2_b, out, ROWS, Cc, CH, out);
}